// round 10
// baseline (speedup 1.0000x reference)
#include <cuda_runtime.h>
#include <cstdint>

// Fixed shapes
#define HH 256
#define WW 512
#define HW (HH * WW)                 // floats per plane
#define HW4 (HW / 4)                 // 32768 float4/plane
#define W4 (WW / 4)                  // 128 float4/row
#define NSTUFF 11
#define STUFF4 (NSTUFF * HW4)
#define TPB 256
#define ITEMS 8                      // float4 per thread per chunk
#define F4C (TPB * ITEMS)            // 2048 float4 = 32 KB = 16 rows
#define ROWS_PER_CHUNK 16
#define STUFF_CHUNKS (STUFF4 / F4C)          // 176
#define CHUNKS_PER_PLANE (HW4 / F4C)         // 16
#define NBOX 128
#define ZBUF_BYTES 4096
#define ZSLICES (F4C * 16 / ZBUF_BYTES)      // 8 bulk stores of 4 KB per chunk

__device__ __forceinline__ uint32_t smem_u32(const void* p) {
    return (uint32_t)__cvta_generic_to_shared(p);
}

__global__ __launch_bounds__(TPB) void seg_term_kernel(
    const int*    __restrict__ cls,     // [128]
    const float*  __restrict__ seg,     // [19*HW]
    const float*  __restrict__ boxes,   // [128*5]
    float*        __restrict__ out)
{
    __shared__ __align__(128) float4 zbuf[ZBUF_BYTES / 16];   // 4 KB of zeros

    const int tid = threadIdx.x;
    const int ch  = blockIdx.x;
    const float4 z = make_float4(0.f, 0.f, 0.f, 0.f);

    if (ch < STUFF_CHUNKS) {
        // ---- stuff copy chunk: 8 batched loads, 8 stores (proven path) ----
        const float4* s4 = reinterpret_cast<const float4*>(seg) + ch * F4C;
        float4*       o4 = reinterpret_cast<float4*>(out)       + ch * F4C;
        float4 v[ITEMS];
        #pragma unroll
        for (int k = 0; k < ITEMS; k++) v[k] = s4[tid + k * TPB];
        #pragma unroll
        for (int k = 0; k < ITEMS; k++) o4[tid + k * TPB] = v[k];
        return;
    }

    const int ic  = ch - STUFF_CHUNKS;
    const int n   = ic >> 4;                     // plane index
    const int blk = ic & (CHUNKS_PER_PLANE - 1);
    const int r0  = blk * ROWS_PER_CHUNK;

    float4* o4 = reinterpret_cast<float4*>(out) + STUFF4 + n * HW4 + blk * F4C;

    // Resolve box first (uniform across CTA)
    const int c = __ldg(cls + n);
    int x0 = 0, y0 = 0, x1 = 0, y1 = 0, m = -1;
    if (c != 0) {
        const float* bb = boxes + n * 5;
        x0 = (int)floorf(__ldg(bb + 1) * 0.25f);
        y0 = (int)floorf(__ldg(bb + 2) * 0.25f);
        x1 = (int)(rintf(__ldg(bb + 3) * 0.25f) + 1.0f);  // half-even = jnp.round
        y1 = (int)(rintf(__ldg(bb + 4) * 0.25f) + 1.0f);
        if (x1 > x0 && y1 > y0 && x1 > 0 && x0 < WW && y1 > 0 && y0 < HH)
            m = (c + 10 > 18) ? 18 : c + 10;
    }

    const bool inter = (m >= 0) && (y1 > r0) && (y0 < r0 + ROWS_PER_CHUNK);

    if (!inter) {
        // ---- pure-zero chunk: 8× 4 KB TMA bulk stores from one 4 KB buffer ----
        zbuf[tid] = z;                            // 1 STS.128 per thread
        __syncthreads();
        if (tid == 0) {
            asm volatile("fence.proxy.async.shared::cta;" ::: "memory");
            const uint32_t src = smem_u32(zbuf);
            char* dst = reinterpret_cast<char*>(o4);
            #pragma unroll
            for (int s = 0; s < ZSLICES; s++) {
                asm volatile(
                    "cp.async.bulk.global.shared::cta.bulk_group [%0], [%1], %2;"
                    :: "l"(dst + s * ZBUF_BYTES), "r"(src), "n"(ZBUF_BYTES)
                    : "memory");
            }
            asm volatile("cp.async.bulk.commit_group;" ::: "memory");
            asm volatile("cp.async.bulk.wait_group 0;" ::: "memory");
        }
        return;
    }

    // ---- box-intersecting chunk: proven gather/mask STG path ----
    const float4* s4 = reinterpret_cast<const float4*>(seg) + m * HW4 + blk * F4C;

    const int x = (tid & (W4 - 1)) << 2;         // first scalar col of this float4
    const bool col_full = (x >= x0) && ((x + 3) < x1);
    const bool col_edge = !col_full && ((x + 3) >= x0) && (x < x1);

    float4 v[ITEMS];
    #pragma unroll
    for (int k = 0; k < ITEMS; k++) {
        const int idx = tid + k * TPB;
        const int y   = r0 + (idx >> 7);
        v[k] = z;
        if (y >= y0 && y < y1) {
            if (col_full) {
                v[k] = s4[idx];
            } else if (col_edge) {
                const float* sr = reinterpret_cast<const float*>(s4 + idx);
                float vv[4];
                #pragma unroll
                for (int j = 0; j < 4; j++) {
                    const int xx = x + j;
                    vv[j] = (xx >= x0 && xx < x1) ? sr[j] : 0.f;
                }
                v[k] = make_float4(vv[0], vv[1], vv[2], vv[3]);
            }
        }
    }
    #pragma unroll
    for (int k = 0; k < ITEMS; k++) o4[tid + k * TPB] = v[k];
}

extern "C" void kernel_launch(void* const* d_in, const int* in_sizes, int n_in,
                              void* d_out, int out_size)
{
    const int*   cls   = (const int*)d_in[0];
    const float* seg   = (const float*)d_in[1];
    const float* boxes = (const float*)d_in[2];
    float* out = (float*)d_out;

    const int blocks = STUFF_CHUNKS + NBOX * CHUNKS_PER_PLANE;  // 2224
    seg_term_kernel<<<blocks, TPB>>>(cls, seg, boxes, out);
}

// round 11
// speedup vs baseline: 1.1040x; 1.1040x over previous
#include <cuda_runtime.h>
#include <cstdint>

// Fixed shapes
#define HH 256
#define WW 512
#define HW (HH * WW)                 // floats per plane
#define HW4 (HW / 4)                 // 32768 float4/plane
#define W4 (WW / 4)                  // 128 float4/row
#define NSTUFF 11
#define STUFF4 (NSTUFF * HW4)
#define TPB 256
#define ITEMS 8                      // float4 per thread per chunk
#define F4_PER_CHUNK (TPB * ITEMS)   // 2048 float4 = 32 KB = 16 rows
#define CHUNK_BYTES (F4_PER_CHUNK * 16)
#define ROWS_PER_CHUNK 16
#define STUFF_CHUNKS (STUFF4 / F4_PER_CHUNK)     // 176
#define CHUNKS_PER_PLANE (HW4 / F4_PER_CHUNK)    // 16
#define NBOX 128

__device__ __forceinline__ uint32_t smem_u32(const void* p) {
    return (uint32_t)__cvta_generic_to_shared(p);
}

__global__ __launch_bounds__(TPB) void seg_term_kernel(
    const int*    __restrict__ cls,     // [128]
    const float*  __restrict__ seg,     // [19*HW]
    const float*  __restrict__ boxes,   // [128*5]
    float*        __restrict__ out)
{
    __shared__ __align__(128) float4 zbuf[F4_PER_CHUNK];   // 32 KB of zeros (TMA source)

    const int tid = threadIdx.x;
    const int ch  = blockIdx.x;
    const float4 z = make_float4(0.f, 0.f, 0.f, 0.f);

    if (ch < STUFF_CHUNKS) {
        // ---- stuff copy chunk: 8 batched LDG.128, then 8 STG.128 ----
        const float4* s4 = reinterpret_cast<const float4*>(seg) + ch * F4_PER_CHUNK;
        float4*       o4 = reinterpret_cast<float4*>(out)       + ch * F4_PER_CHUNK;
        float4 v[ITEMS];
        #pragma unroll
        for (int k = 0; k < ITEMS; k++) v[k] = s4[tid + k * TPB];
        #pragma unroll
        for (int k = 0; k < ITEMS; k++) o4[tid + k * TPB] = v[k];
        return;
    }

    // Zero the SMEM buffer up front — independent work that overlaps the
    // dependent cls/boxes load chain below.
    #pragma unroll
    for (int k = 0; k < ITEMS; k++) zbuf[tid + k * TPB] = z;

    const int ic  = ch - STUFF_CHUNKS;
    const int n   = ic >> 4;                     // plane index
    const int blk = ic & (CHUNKS_PER_PLANE - 1);
    const int r0  = blk * ROWS_PER_CHUNK;

    float4* o4 = reinterpret_cast<float4*>(out) + STUFF4 + n * HW4 + blk * F4_PER_CHUNK;

    const int c = __ldg(cls + n);
    int x0 = 0, y0 = 0, x1 = 0, y1 = 0, m = -1;
    if (c != 0) {
        const float* bb = boxes + n * 5;
        x0 = (int)floorf(__ldg(bb + 1) * 0.25f);
        y0 = (int)floorf(__ldg(bb + 2) * 0.25f);
        x1 = (int)(rintf(__ldg(bb + 3) * 0.25f) + 1.0f);  // half-even = jnp.round
        y1 = (int)(rintf(__ldg(bb + 4) * 0.25f) + 1.0f);
        if (x1 > x0 && y1 > y0 && x1 > 0 && x0 < WW && y1 > 0 && y0 < HH)
            m = (c + 10 > 18) ? 18 : c + 10;
    }

    const bool inter = (m >= 0) && (y1 > r0) && (y0 < r0 + ROWS_PER_CHUNK);

    if (!inter) {
        // ---- pure-zero chunk: ONE 32 KB TMA bulk store from SMEM ----
        __syncthreads();                                   // zbuf writes visible
        if (tid == 0) {
            asm volatile("fence.proxy.async.shared::cta;" ::: "memory");
            asm volatile(
                "cp.async.bulk.global.shared::cta.bulk_group [%0], [%1], %2;"
                :: "l"(o4), "r"(smem_u32(zbuf)), "n"(CHUNK_BYTES)
                : "memory");
            asm volatile("cp.async.bulk.commit_group;" ::: "memory");
            asm volatile("cp.async.bulk.wait_group 0;" ::: "memory");
        }
        return;
    }

    // ---- box-intersecting chunk: gather/mask STG path ----
    const float4* s4 = reinterpret_cast<const float4*>(seg) + m * HW4 + blk * F4_PER_CHUNK;

    const int x = (tid & (W4 - 1)) << 2;          // first scalar col of this float4
    const bool col_full = (x >= x0) && ((x + 3) < x1);
    const bool col_edge = !col_full && ((x + 3) >= x0) && (x < x1);

    float4 v[ITEMS];
    #pragma unroll
    for (int k = 0; k < ITEMS; k++) {
        const int idx = tid + k * TPB;
        const int y   = r0 + (idx >> 7);
        v[k] = z;
        if (y >= y0 && y < y1) {
            if (col_full) {
                v[k] = s4[idx];
            } else if (col_edge) {
                const float* sr = reinterpret_cast<const float*>(s4 + idx);
                float vv[4];
                #pragma unroll
                for (int j = 0; j < 4; j++) {
                    const int xx = x + j;
                    vv[j] = (xx >= x0 && xx < x1) ? sr[j] : 0.f;
                }
                v[k] = make_float4(vv[0], vv[1], vv[2], vv[3]);
            }
        }
    }
    #pragma unroll
    for (int k = 0; k < ITEMS; k++) o4[tid + k * TPB] = v[k];
}

extern "C" void kernel_launch(void* const* d_in, const int* in_sizes, int n_in,
                              void* d_out, int out_size)
{
    const int*   cls   = (const int*)d_in[0];
    const float* seg   = (const float*)d_in[1];
    const float* boxes = (const float*)d_in[2];
    float* out = (float*)d_out;

    const int blocks = STUFF_CHUNKS + NBOX * CHUNKS_PER_PLANE;  // 2224
    seg_term_kernel<<<blocks, TPB>>>(cls, seg, boxes, out);
}

// round 12
// speedup vs baseline: 1.1207x; 1.0151x over previous
#include <cuda_runtime.h>

// Fixed shapes
#define HH 256
#define WW 512
#define HW (HH * WW)                 // 131072 floats/plane
#define HW4 (HW / 4)                 // 32768 float4/plane
#define W4 (WW / 4)                  // 128 float4/row
#define NSTUFF 11
#define STUFF4 (NSTUFF * HW4)        // 360448 float4
#define ITEMS 8                      // float4 per thread
#define TPB 256
#define F4_PER_BLK (TPB * ITEMS)     // 2048 float4 per block (= 16 rows)
#define ROWS_PER_BLK (F4_PER_BLK / W4)       // 16
#define STUFF_BLOCKS (STUFF4 / F4_PER_BLK)   // 176 (exact)
#define BLOCKS_PER_PLANE (HW4 / F4_PER_BLK)  // 16 (exact)
#define NBOX 128

__global__ __launch_bounds__(TPB) void seg_term_kernel(
    const int*    __restrict__ cls,     // [128]
    const float*  __restrict__ seg,     // [19*HW]
    const float*  __restrict__ boxes,   // [128*5]
    float*        __restrict__ out)     // [STUFF4*4 + 128*HW]
{
    const int b   = blockIdx.x;
    const int tid = threadIdx.x;
    const float4 z = make_float4(0.f, 0.f, 0.f, 0.f);

    if (b < STUFF_BLOCKS) {
        // ---- stuff copy: 8 batched loads, then 8 stores (MLP=8) ----
        const float4* s4 = reinterpret_cast<const float4*>(seg) + b * F4_PER_BLK;
        float4*       o4 = reinterpret_cast<float4*>(out)       + b * F4_PER_BLK;
        float4 v[ITEMS];
        #pragma unroll
        for (int k = 0; k < ITEMS; k++) v[k] = s4[tid + k * TPB];
        #pragma unroll
        for (int k = 0; k < ITEMS; k++) o4[tid + k * TPB] = v[k];
        return;
    }

    // ---- instance region: each block owns 16 rows of ONE plane ----
    const int ib  = b - STUFF_BLOCKS;
    const int n   = ib >> 4;                     // plane (16 blocks/plane)
    const int blk = ib & (BLOCKS_PER_PLANE - 1);
    const int r0  = blk * ROWS_PER_BLK;          // first row of this block

    float4* o4 = reinterpret_cast<float4*>(out) + STUFF4 + n * HW4 + blk * F4_PER_BLK;

    const int c = __ldg(cls + n);

    int x0 = 0, y0 = 0, x1 = 0, y1 = 0, m = 0;
    bool any = false;
    if (c != 0) {
        const float* bb = boxes + n * 5;
        x0 = (int)floorf(__ldg(bb + 1) * 0.25f);
        y0 = (int)floorf(__ldg(bb + 2) * 0.25f);
        x1 = (int)(rintf(__ldg(bb + 3) * 0.25f) + 1.0f);  // half-even, matches jnp.round
        y1 = (int)(rintf(__ldg(bb + 4) * 0.25f) + 1.0f);
        m  = (c + 10 > 18) ? 18 : c + 10;
        // does this block's row range [r0, r0+16) intersect [y0, y1)?
        any = (y1 > r0) && (y0 < r0 + ROWS_PER_BLK) && (x1 > x0) && (x1 > 0) && (x0 < WW);
    }

    if (!any) {
        // pure zero-fill burst
        #pragma unroll
        for (int k = 0; k < ITEMS; k++) o4[tid + k * TPB] = z;
        return;
    }

    const float4* s4 = reinterpret_cast<const float4*>(seg) + m * HW4 + blk * F4_PER_BLK;

    // Phase 1: compute all 8 values; loads batched up front by ptxas.
    float4 v[ITEMS];
    #pragma unroll
    for (int k = 0; k < ITEMS; k++) {
        const int idx = tid + k * TPB;           // float4 index within chunk
        const int y   = r0 + (idx >> 7);         // global row
        const int x   = (idx & (W4 - 1)) << 2;   // first col of this float4

        v[k] = z;
        if (y >= y0 && y < y1) {
            if (x >= x0 && (x + 3) < x1) {
                v[k] = s4[idx];                  // fully inside
            } else if ((x + 3) >= x0 && x < x1) {
                const float* sr = reinterpret_cast<const float*>(s4 + idx);
                float vv[4];
                #pragma unroll
                for (int j = 0; j < 4; j++) {
                    const int xx = x + j;
                    vv[j] = (xx >= x0 && xx < x1) ? sr[j] : 0.f;
                }
                v[k] = make_float4(vv[0], vv[1], vv[2], vv[3]);
            }
        }
    }
    // Phase 2: store burst
    #pragma unroll
    for (int k = 0; k < ITEMS; k++) o4[tid + k * TPB] = v[k];
}

extern "C" void kernel_launch(void* const* d_in, const int* in_sizes, int n_in,
                              void* d_out, int out_size)
{
    const int*   cls   = (const int*)d_in[0];
    const float* seg   = (const float*)d_in[1];
    const float* boxes = (const float*)d_in[2];
    float* out = (float*)d_out;

    const int blocks = STUFF_BLOCKS + NBOX * BLOCKS_PER_PLANE;  // 176 + 2048 = 2224
    seg_term_kernel<<<blocks, TPB>>>(cls, seg, boxes, out);
}